// round 3
// baseline (speedup 1.0000x reference)
#include <cuda_runtime.h>

#define O_TOTAL 16384

// Scratch (device global — no allocation allowed)
__device__ float g_Aw[128 * 64];          // [h][b], A = (pz@W1_h) premultiplied by |W2[h]|

// ---------- packed f32x2 helpers ----------
__device__ __forceinline__ unsigned long long pack2(float x, float y) {
    unsigned long long u;
    asm("mov.b64 %0, {%1,%2};" : "=l"(u) : "f"(x), "f"(y));
    return u;
}
__device__ __forceinline__ void unpack2(unsigned long long u, float &x, float &y) {
    asm("mov.b64 {%0,%1}, %2;" : "=f"(x), "=f"(y) : "l"(u));
}
__device__ __forceinline__ unsigned long long add2(unsigned long long a, unsigned long long b) {
    unsigned long long d;
    asm("add.rn.f32x2 %0, %1, %2;" : "=l"(d) : "l"(a), "l"(b));
    return d;
}
__device__ __forceinline__ unsigned long long fma2(unsigned long long a, unsigned long long b, unsigned long long c) {
    unsigned long long d;
    asm("fma.rn.f32x2 %0, %1, %2, %3;" : "=l"(d) : "l"(a), "l"(b), "l"(c));
    return d;
}
__device__ __forceinline__ unsigned long long relu2(unsigned long long v) {
    float x, y;
    unpack2(v, x, y);
    x = fmaxf(x, 0.0f);
    y = fmaxf(y, 0.0f);
    return pack2(x, y);
}

// =====================================================================
// Kernel A: 16 CTAs. Each computes pz = relu(z@Wz+bz) (redundantly),
//           then its 8 h-rows of Aw[h,b] = (pz@W1_h)[b,h] * |W2[h]|.
// =====================================================================
#define A_SMEM 58368

__global__ void __launch_bounds__(512) k_A(
    const float* __restrict__ z,  const float* __restrict__ Wz,
    const float* __restrict__ bz, const float* __restrict__ W1,
    const float* __restrict__ W2)
{
    extern __shared__ float sm[];
    float* zs  = sm;                   // [b][k]  64x32
    float* Wzs = sm + 64 * 32;         // [k][h]  32x128
    float* bzs = Wzs + 32 * 128;       // [h]
    float* pzT = bzs + 128;            // [k][b]  pitch 65

    int tid = threadIdx.x;
    int cta = blockIdx.x;              // 0..15, h-tile [8*cta, 8*cta+8)

    for (int i = tid; i < 64 * 32; i += 512)  zs[i]  = z[i];
    for (int i = tid; i < 32 * 128; i += 512) Wzs[i] = Wz[i];
    for (int i = tid; i < 128; i += 512)      bzs[i] = bz[i];
    __syncthreads();

    // pz = relu(z@Wz + bz), stored transposed [h][b] pitch 65
    for (int i = tid; i < 64 * 128; i += 512) {
        int b = i >> 7, hh = i & 127;
        float a = bzs[hh];
#pragma unroll
        for (int k = 0; k < 32; k++)
            a += zs[b * 32 + k] * Wzs[k * 128 + hh];
        pzT[hh * 65 + b] = fmaxf(a, 0.0f);
    }
    __syncthreads();

    // Aw[h,b] = (pz @ W1_h)[b,h] * |W2[h]|
    int h = cta * 8 + (tid >> 6);
    int b = tid & 63;
    float a = 0.0f;
#pragma unroll 8
    for (int k = 0; k < 128; k++)
        a += pzT[k * 65 + b] * W1[k * 128 + h];
    g_Aw[h * 64 + b] = a * fabsf(W2[h]);
}

// =====================================================================
// Kernel main: 128 CTAs x 1024 threads. CTA t handles o-tile
// [t*128, t*128+128), all 64 b. Preamble computes its G tile in smem:
//   G[o,h] = (fe@W1_f + fb*W1_b + b1)[o,h] * |W2[h]|
// Then:  out[b,o] = sum_h sgn(W2[h]) * max(Aw[h,b] + G[o,h], 0) + b2
// =====================================================================
// smem: As2 (dup pairs, 64KB) | Gs (64KB) | s2 (1KB). Staging overlays As2.
#define MAIN_SMEM (128 * 64 * 8 + 128 * 128 * 4 + 128 * 8)   // 132096

__global__ void __launch_bounds__(1024) k_main(
    const float* __restrict__ fe, const float* __restrict__ fb,
    const float* __restrict__ W1, const float* __restrict__ b1,
    const float* __restrict__ W2, const float* __restrict__ b2,
    float* __restrict__ out)
{
    extern __shared__ float sm[];
    unsigned long long* As2 = (unsigned long long*)sm;             // [h][b] dup pairs
    float* Gs = sm + 2 * 128 * 64;                                 // [h][o]
    unsigned long long* s2 = (unsigned long long*)(Gs + 128 * 128);
    // staging overlay (lives in As2 region until G is computed)
    float* W1fs = sm;                  // [c][h]  32x128 (16KB)
    float* fes  = sm + 32 * 128;       // [c][o]  pitch 129 (~16.5KB)

    int tid = threadIdx.x;
    int t = blockIdx.x;

    // ---- stage fe tile + W1_f + signs ----
    for (int i = tid; i < 32 * 128; i += 1024) W1fs[i] = W1[128 * 128 + i];
    for (int i = tid; i < 128 * 32; i += 1024) {
        int o = i >> 5, c = i & 31;
        fes[c * 129 + o] = fe[(t * 128 + o) * 32 + c];
    }
    if (tid < 128) {
        float w = W2[tid];
        float s = (w >= 0.0f) ? 1.0f : -1.0f;
        s2[tid] = pack2(s, s);
    }
    __syncthreads();

    // ---- compute G tile into Gs ----
    {
        int ol = tid & 127;            // o_local
        int hc = tid >> 7;             // h-chunk 0..7 (16 h each)
        unsigned long long acc[8];
#pragma unroll
        for (int j = 0; j < 8; j++) acc[j] = 0ull;

#pragma unroll 4
        for (int c = 0; c < 32; c++) {
            float f = fes[c * 129 + ol];
            unsigned long long f2 = pack2(f, f);
            const unsigned long long* wrow =
                (const unsigned long long*)(W1fs + c * 128 + hc * 16);
#pragma unroll
            for (int j = 0; j < 8; j++)
                acc[j] = fma2(f2, wrow[j], acc[j]);
        }

        float fbv = fb[t * 128 + ol];
#pragma unroll
        for (int j = 0; j < 8; j++) {
            int h0 = hc * 16 + 2 * j;
            float ax, ay;
            unpack2(acc[j], ax, ay);
            float g0 = (ax + fbv * W1[160 * 128 + h0]     + b1[h0])     * fabsf(W2[h0]);
            float g1 = (ay + fbv * W1[160 * 128 + h0 + 1] + b1[h0 + 1]) * fabsf(W2[h0 + 1]);
            Gs[h0 * 128 + ol]       = g0;
            Gs[(h0 + 1) * 128 + ol] = g1;
        }
    }
    __syncthreads();   // staging reads done; Gs complete

    // ---- fill As2 (duplicated pairs) over the staging area ----
    for (int i = tid; i < 128 * 64; i += 1024) {
        float a = g_Aw[i];
        As2[i] = pack2(a, a);
    }
    __syncthreads();

    // ---- main loop: per-thread tile 4b x 2o ----
    int og = tid & 63;            // o-pair index: o0 = og*2
    int bg = tid >> 6;            // b-group: b0 = bg*4
    int o0 = og * 2, b0 = bg * 4;

    const ulonglong2* Av = (const ulonglong2*)As2;                 // h*32 + bg*2 (+1)
    const unsigned long long* Gv = (const unsigned long long*)Gs;  // h*64 + og

    unsigned long long acc0 = 0ull, acc1 = 0ull, acc2 = 0ull, acc3 = 0ull;

#pragma unroll 8
    for (int h = 0; h < 128; h++) {
        ulonglong2 a01 = Av[h * 32 + bg * 2];      // {a(b0),a(b0)},{a(b0+1),a(b0+1)}
        ulonglong2 a23 = Av[h * 32 + bg * 2 + 1];  // b0+2, b0+3
        unsigned long long g = Gv[h * 64 + og];    // {g(o0), g(o0+1)}
        unsigned long long sp = s2[h];

        unsigned long long v;
        v = relu2(add2(a01.x, g)); acc0 = fma2(v, sp, acc0);
        v = relu2(add2(a01.y, g)); acc1 = fma2(v, sp, acc1);
        v = relu2(add2(a23.x, g)); acc2 = fma2(v, sp, acc2);
        v = relu2(add2(a23.y, g)); acc3 = fma2(v, sp, acc3);
    }

    float b2v = b2[0];
    float2 r;
    unpack2(acc0, r.x, r.y); r.x += b2v; r.y += b2v;
    *(float2*)(out + (b0 + 0) * O_TOTAL + t * 128 + o0) = r;
    unpack2(acc1, r.x, r.y); r.x += b2v; r.y += b2v;
    *(float2*)(out + (b0 + 1) * O_TOTAL + t * 128 + o0) = r;
    unpack2(acc2, r.x, r.y); r.x += b2v; r.y += b2v;
    *(float2*)(out + (b0 + 2) * O_TOTAL + t * 128 + o0) = r;
    unpack2(acc3, r.x, r.y); r.x += b2v; r.y += b2v;
    *(float2*)(out + (b0 + 3) * O_TOTAL + t * 128 + o0) = r;
}

extern "C" void kernel_launch(void* const* d_in, const int* in_sizes, int n_in,
                              void* d_out, int out_size) {
    (void)in_sizes; (void)n_in; (void)out_size;
    const float* z  = (const float*)d_in[0];
    const float* fe = (const float*)d_in[1];
    const float* fb = (const float*)d_in[2];
    const float* Wz = (const float*)d_in[3];
    const float* bz = (const float*)d_in[4];
    const float* W1 = (const float*)d_in[5];
    const float* b1 = (const float*)d_in[6];
    const float* W2 = (const float*)d_in[7];
    const float* b2 = (const float*)d_in[8];
    float* out = (float*)d_out;

    cudaFuncSetAttribute(k_A,    cudaFuncAttributeMaxDynamicSharedMemorySize, A_SMEM);
    cudaFuncSetAttribute(k_main, cudaFuncAttributeMaxDynamicSharedMemorySize, MAIN_SMEM);

    k_A<<<16, 512, A_SMEM>>>(z, Wz, bz, W1, W2);
    k_main<<<128, 1024, MAIN_SMEM>>>(fe, fb, W1, b1, W2, b2, out);
}